// round 1
// baseline (speedup 1.0000x reference)
#include <cuda_runtime.h>
#include <math.h>

#define NB 8
#define NC 20
#define NP 8732
#define NM 16
#define THREADS 256
#define THRESH 0.5f

// global accumulators (per class)
__device__ float g_conf[NC];
__device__ float g_l1[NC];
__device__ float g_npos[NC];

__global__ void mb_init_kernel() {
    int i = threadIdx.x;
    if (i < NC) { g_conf[i] = 0.f; g_l1[i] = 0.f; g_npos[i] = 0.f; }
}

__global__ __launch_bounds__(THREADS) void mb_main_kernel(
    const float* __restrict__ ploc,    // (N,C,P,4)
    const float* __restrict__ pscore,  // (N,C,P,2)
    const float* __restrict__ boxes,   // (N,C,M,4) xy
    const int*   __restrict__ labels,  // (N,C,M)
    const float* __restrict__ priors)  // (P,4) cxcywh
{
    __shared__ float          s_ce[NP];     // ov, then ce_neg
    __shared__ unsigned char  s_obj[NP];
    __shared__ float          s_bx[NM][5];  // x1,y1,x2,y2,area
    __shared__ int            s_lab[NM];
    __shared__ unsigned long long s_best[NM];
    __shared__ unsigned int   s_hist[256];
    __shared__ float          s_l1sum, s_cpsum, s_sumgt;
    __shared__ int            s_npos, s_kk;
    __shared__ unsigned int   s_pref;

    const int bc  = blockIdx.x;          // n*NC + c
    const int c   = bc % NC;
    const int tid = threadIdx.x;

    // ---- load boxes / labels ----
    if (tid < NM) {
        const float* b = boxes + ((size_t)bc * NM + tid) * 4;
        float x1 = b[0], y1 = b[1], x2 = b[2], y2 = b[3];
        s_bx[tid][0] = x1; s_bx[tid][1] = y1;
        s_bx[tid][2] = x2; s_bx[tid][3] = y2;
        s_bx[tid][4] = (x2 - x1) * (y2 - y1);
        s_lab[tid]  = labels[(size_t)bc * NM + tid];
        s_best[tid] = 0ull;
    }
    if (tid == 0) { s_npos = 0; s_l1sum = 0.f; s_cpsum = 0.f; s_sumgt = 0.f; }
    __syncthreads();

    // ---- pass 1: IoU, per-prior max/argmax over M, per-box best over P ----
    unsigned long long best[NM];
#pragma unroll
    for (int m = 0; m < NM; m++) best[m] = 0ull;

    for (int p = tid; p < NP; p += THREADS) {
        float4 pr = reinterpret_cast<const float4*>(priors)[p];
        float px1 = pr.x - pr.z * 0.5f, py1 = pr.y - pr.w * 0.5f;
        float px2 = pr.x + pr.z * 0.5f, py2 = pr.y + pr.w * 0.5f;
        float parea = (px2 - px1) * (py2 - py1);
        float bestv = -1.f; int bestm = 0;
#pragma unroll
        for (int m = 0; m < NM; m++) {
            float iw = fminf(s_bx[m][2], px2) - fmaxf(s_bx[m][0], px1);
            float ih = fminf(s_bx[m][3], py2) - fmaxf(s_bx[m][1], py1);
            iw = fmaxf(iw, 0.f); ih = fmaxf(ih, 0.f);
            float inter = iw * ih;
            float iou = inter / (s_bx[m][4] + parea - inter);
            if (iou > bestv) { bestv = iou; bestm = m; }  // first max wins
            unsigned long long key =
                ((unsigned long long)__float_as_uint(iou) << 32) |
                (unsigned)(NP - 1 - p);  // tie -> lowest p
            best[m] = key > best[m] ? key : best[m];
        }
        s_ce[p]  = bestv;                 // ov_for_prior (for now)
        s_obj[p] = (unsigned char)bestm;
    }
#pragma unroll
    for (int m = 0; m < NM; m++) atomicMax(&s_best[m], best[m]);
    __syncthreads();

    // ---- forced matching: sequential last-write-wins, like XLA scatter ----
    if (tid == 0) {
        for (int m = 0; m < NM; m++) {
            int pp = NP - 1 - (int)(s_best[m] & 0xFFFFFFFFu);
            s_obj[pp] = (unsigned char)m;
            s_ce[pp]  = 1.0f;
        }
    }
    __syncthreads();

    // ---- pass 2: ce, positives (L1 + conf), write ce_neg ----
    float l1_acc = 0.f, cp_acc = 0.f; int np_acc = 0;
    for (int p = tid; p < NP; p += THREADS) {
        float ov = s_ce[p];
        int m = s_obj[p];
        int cls = (ov < THRESH) ? 0 : s_lab[m];
        float2 sc = reinterpret_cast<const float2*>(pscore)[(size_t)bc * NP + p];
        float mx  = fmaxf(sc.x, sc.y);
        float lse = mx + logf(expf(sc.x - mx) + expf(sc.y - mx));
        float ce  = lse - (cls ? sc.y : sc.x);
        if (cls != 0) {
            np_acc++;
            cp_acc += ce;
            float4 pr = reinterpret_cast<const float4*>(priors)[p];
            float bx1 = s_bx[m][0], by1 = s_bx[m][1];
            float bx2 = s_bx[m][2], by2 = s_bx[m][3];
            float cx = (bx1 + bx2) * 0.5f, cy = (by1 + by2) * 0.5f;
            float w  = bx2 - bx1,          h  = by2 - by1;
            float gx = (cx - pr.x) / (pr.z / 10.f);
            float gy = (cy - pr.y) / (pr.w / 10.f);
            float gw = logf(w / pr.z) * 5.f;
            float gh = logf(h / pr.w) * 5.f;
            float4 pl = reinterpret_cast<const float4*>(ploc)[(size_t)bc * NP + p];
            l1_acc += fabsf(pl.x - gx) + fabsf(pl.y - gy) +
                      fabsf(pl.z - gw) + fabsf(pl.w - gh);
            ce = 0.f;   // positives contribute 0 to ce_neg
        }
        s_ce[p] = ce;
    }
    atomicAdd(&s_l1sum, l1_acc);
    atomicAdd(&s_cpsum, cp_acc);
    atomicAdd(&s_npos,  np_acc);
    __syncthreads();

    const int npos = s_npos;
    const int K = 3 * npos;
    float conf_hard = 0.f;

    // ---- radix select: exact sum of top-K of s_ce (all values >= 0) ----
    if (K > 0) {
        if (tid == 0) { s_pref = 0u; s_kk = K; }
        __syncthreads();
        for (int pass = 3; pass >= 0; pass--) {
            int shift = pass * 8;
            for (int i = tid; i < 256; i += THREADS) s_hist[i] = 0u;
            __syncthreads();
            unsigned pref   = s_pref;
            unsigned maskHi = (pass == 3) ? 0u : (0xFFFFFFFFu << (shift + 8));
            for (int p = tid; p < NP; p += THREADS) {
                unsigned key = __float_as_uint(s_ce[p]);
                if ((key & maskHi) == pref)
                    atomicAdd(&s_hist[(key >> shift) & 0xFF], 1u);
            }
            __syncthreads();
            if (tid == 0) {
                int kk = s_kk; unsigned cum = 0;
                for (int b = 255; b >= 0; b--) {
                    unsigned hcnt = s_hist[b];
                    if (cum + hcnt >= (unsigned)kk) {
                        s_pref = pref | ((unsigned)b << shift);
                        s_kk   = kk - (int)cum;
                        break;
                    }
                    cum += hcnt;
                }
            }
            __syncthreads();
        }
        unsigned T = s_pref;
        float sum_gt = 0.f;
        for (int p = tid; p < NP; p += THREADS) {
            float v = s_ce[p];
            if (__float_as_uint(v) > T) sum_gt += v;
        }
        atomicAdd(&s_sumgt, sum_gt);
        __syncthreads();
        if (tid == 0)
            conf_hard = s_sumgt + (float)s_kk * __uint_as_float(T);
    }

    if (tid == 0) {
        atomicAdd(&g_conf[c], s_cpsum + conf_hard);
        atomicAdd(&g_l1[c],   s_l1sum);
        atomicAdd(&g_npos[c], (float)npos);
    }
}

__global__ void mb_finalize_kernel(float* __restrict__ out) {
    if (threadIdx.x == 0 && blockIdx.x == 0) {
        float s = 0.f;
        for (int c = 0; c < NC; c++) {
            float np = g_npos[c];
            if (np > 0.f) {
                float loc = g_l1[c] / fmaxf(np * 4.f, 1.f);
                s += (g_conf[c] + 1.0f * loc) / fmaxf(np, 1.f);
            }
        }
        out[0] = s / (float)NC;
    }
}

extern "C" void kernel_launch(void* const* d_in, const int* in_sizes, int n_in,
                              void* d_out, int out_size) {
    const float* ploc   = (const float*)d_in[0];
    const float* pscore = (const float*)d_in[1];
    const float* boxes  = (const float*)d_in[2];
    const int*   labels = (const int*)d_in[3];
    const float* priors = (const float*)d_in[4];
    float* out = (float*)d_out;

    mb_init_kernel<<<1, 32>>>();
    mb_main_kernel<<<NB * NC, THREADS>>>(ploc, pscore, boxes, labels, priors);
    mb_finalize_kernel<<<1, 32>>>(out);
}

// round 2
// speedup vs baseline: 3.9869x; 3.9869x over previous
#include <cuda_runtime.h>
#include <math.h>

#define NB 8
#define NC 20
#define NROWS (NB * NC)
#define NP 8732
#define NM 16
#define THREADS 512
#define THRESH 0.5f

// per-(n,c) partials, overwritten each run (no init kernel needed)
__device__ float g_conf_p[NROWS];
__device__ float g_l1_p[NROWS];
__device__ float g_np_p[NROWS];

__device__ __forceinline__ float warp_sum(float v) {
#pragma unroll
    for (int o = 16; o; o >>= 1) v += __shfl_down_sync(0xffffffffu, v, o);
    return v;
}

__global__ __launch_bounds__(THREADS, 1) void mb_main_kernel(
    const float* __restrict__ ploc,    // (N,C,P,4)
    const float* __restrict__ pscore,  // (N,C,P,2)
    const float* __restrict__ boxes,   // (N,C,M,4) xy
    const int*   __restrict__ labels,  // (N,C,M)
    const float* __restrict__ priors)  // (P,4) cxcywh
{
    __shared__ float          s_ce[NP];     // ov, then ce_neg
    __shared__ unsigned char  s_obj[NP];
    __shared__ float4         s_bx4[NM];    // x1,y1,x2,y2
    __shared__ float          s_area[NM];
    __shared__ int            s_lab[NM];
    __shared__ unsigned long long s_best[NM];
    __shared__ unsigned int   s_hist[256];
    __shared__ float          s_l1sum, s_cpsum, s_sumgt;
    __shared__ int            s_npos, s_kk;
    __shared__ unsigned int   s_pref;

    const int bc   = blockIdx.x;          // n*NC + c
    const int tid  = threadIdx.x;
    const int lane = tid & 31;
    const float4* __restrict__ prior4 = reinterpret_cast<const float4*>(priors);

    if (tid < NM) {
        const float* b = boxes + ((size_t)bc * NM + tid) * 4;
        float x1 = b[0], y1 = b[1], x2 = b[2], y2 = b[3];
        s_bx4[tid]  = make_float4(x1, y1, x2, y2);
        s_area[tid] = (x2 - x1) * (y2 - y1);
        s_lab[tid]  = labels[(size_t)bc * NM + tid];
        s_best[tid] = 0ull;
    }
    if (tid == 0) { s_npos = 0; s_l1sum = 0.f; s_cpsum = 0.f; s_sumgt = 0.f; }
    __syncthreads();

    // ---- pass 1: IoU, per-prior argmax over M (2 chunks of 8), per-box best over P ----
#pragma unroll 1
    for (int ch = 0; ch < 2; ch++) {
        const int mbase = ch * 8;
        float bx1[8], by1[8], bx2[8], by2[8], ba[8];
#pragma unroll
        for (int i = 0; i < 8; i++) {
            float4 b = s_bx4[mbase + i];
            bx1[i] = b.x; by1[i] = b.y; bx2[i] = b.z; by2[i] = b.w;
            ba[i] = s_area[mbase + i];
        }
        float bv[8]; int bp[8];
#pragma unroll
        for (int i = 0; i < 8; i++) { bv[i] = -1.f; bp[i] = 0; }

        for (int p = tid; p < NP; p += THREADS) {
            float4 pr = prior4[p];
            float hw = pr.z * 0.5f, hh = pr.w * 0.5f;
            float px1 = pr.x - hw, py1 = pr.y - hh;
            float px2 = pr.x + hw, py2 = pr.y + hh;
            float parea = (px2 - px1) * (py2 - py1);
            float bestv; int bestm;
            if (ch == 0) { bestv = -1.f; bestm = 0; }
            else         { bestv = s_ce[p]; bestm = s_obj[p]; }
#pragma unroll
            for (int i = 0; i < 8; i++) {
                float iw = fminf(bx2[i], px2) - fmaxf(bx1[i], px1);
                float ih = fminf(by2[i], py2) - fmaxf(by1[i], py1);
                iw = fmaxf(iw, 0.f); ih = fmaxf(ih, 0.f);
                float inter = iw * ih;
                float iou = __fdividef(inter, ba[i] + parea - inter);
                if (iou > bestv) { bestv = iou; bestm = mbase + i; }
                if (iou > bv[i]) { bv[i]  = iou; bp[i]  = p; }
            }
            s_ce[p]  = bestv;
            s_obj[p] = (unsigned char)bestm;
        }
#pragma unroll
        for (int i = 0; i < 8; i++) {
            unsigned long long key =
                ((unsigned long long)__float_as_uint(fmaxf(bv[i], 0.f)) << 32) |
                (unsigned)(NP - 1 - bp[i]);   // tie -> lowest p
            atomicMax(&s_best[mbase + i], key);
        }
    }
    __syncthreads();

    // ---- forced matching: sequential last-write-wins (XLA scatter semantics) ----
    if (tid == 0) {
        for (int m = 0; m < NM; m++) {
            int pp = NP - 1 - (int)(s_best[m] & 0xFFFFFFFFu);
            s_obj[pp] = (unsigned char)m;
            s_ce[pp]  = 1.0f;
        }
    }
    __syncthreads();

    // ---- pass 2: CE, positives (L1 + conf), write ce_neg ----
    {
        float l1_acc = 0.f, cp_acc = 0.f; float np_acc = 0.f;
        const float2* __restrict__ sc2 = reinterpret_cast<const float2*>(pscore) + (size_t)bc * NP;
        const float4* __restrict__ pl4 = reinterpret_cast<const float4*>(ploc)   + (size_t)bc * NP;
        for (int p = tid; p < NP; p += THREADS) {
            float ov = s_ce[p];
            int m = s_obj[p];
            int cls = (ov < THRESH) ? 0 : s_lab[m];
            float2 sc = sc2[p];
            float mx = fmaxf(sc.x, sc.y);
            float lse = mx + __logf(1.f + __expf(-fabsf(sc.x - sc.y)));
            float ce = lse - (cls ? sc.y : sc.x);
            if (cls != 0) {
                np_acc += 1.f;
                cp_acc += ce;
                float4 pr = prior4[p];
                float4 b  = s_bx4[m];
                float cx = (b.x + b.z) * 0.5f, cy = (b.y + b.w) * 0.5f;
                float w  = b.z - b.x,          h  = b.w - b.y;
                float gx = __fdividef((cx - pr.x) * 10.f, pr.z);
                float gy = __fdividef((cy - pr.y) * 10.f, pr.w);
                float gw = __logf(__fdividef(w, pr.z)) * 5.f;
                float gh = __logf(__fdividef(h, pr.w)) * 5.f;
                float4 pl = pl4[p];
                l1_acc += fabsf(pl.x - gx) + fabsf(pl.y - gy) +
                          fabsf(pl.z - gw) + fabsf(pl.w - gh);
                ce = 0.f;   // positives contribute 0 to ce_neg
            }
            s_ce[p] = ce;
        }
        l1_acc = warp_sum(l1_acc);
        cp_acc = warp_sum(cp_acc);
        np_acc = warp_sum(np_acc);
        if (lane == 0) {
            atomicAdd(&s_l1sum, l1_acc);
            atomicAdd(&s_cpsum, cp_acc);
            atomicAdd(&s_npos, (int)np_acc);
        }
    }
    __syncthreads();

    const int npos = s_npos;
    int K = 3 * npos;
    if (K > NP) K = NP;
    float conf_hard = 0.f;

    // ---- radix select: exact sum of top-K of s_ce (all values >= 0) ----
    if (K > 0) {
        if (tid == 0) { s_pref = 0u; s_kk = K; }
        __syncthreads();
#pragma unroll 1
        for (int pass = 3; pass >= 0; pass--) {
            const int shift = pass * 8;
            if (tid < 256) s_hist[tid] = 0u;
            __syncthreads();
            const unsigned pref   = s_pref;
            const unsigned maskHi = (pass == 3) ? 0u : (0xFFFFFFFFu << (shift + 8));
            for (int p0 = 0; p0 < NP; p0 += THREADS) {
                int p = p0 + tid;
                bool pred = false; int bin = 0;
                if (p < NP) {
                    unsigned key = __float_as_uint(s_ce[p]);
                    pred = ((key & maskHi) == pref);
                    bin  = (key >> shift) & 0xFF;
                }
                unsigned act = __ballot_sync(0xffffffffu, pred);
                if (pred) {
                    unsigned peers = __match_any_sync(act, bin);
                    if ((__ffs(peers) - 1) == lane)
                        atomicAdd(&s_hist[bin], (unsigned)__popc(peers));
                }
            }
            __syncthreads();
            // single-warp suffix-scan selection over 256 bins
            if (tid < 32) {
                unsigned h[8]; unsigned lsum = 0;
                const int base = (31 - lane) * 8;   // lane 0 -> bins 248..255
#pragma unroll
                for (int i = 0; i < 8; i++) { h[i] = s_hist[base + i]; lsum += h[i]; }
                unsigned incl = lsum;
#pragma unroll
                for (int off = 1; off < 32; off <<= 1) {
                    unsigned v = __shfl_up_sync(0xffffffffu, incl, off);
                    if (lane >= off) incl += v;
                }
                unsigned excl = incl - lsum;        // count in bins strictly above this lane's range
                int kk = s_kk;
                if (excl < (unsigned)kk && incl >= (unsigned)kk) {
                    unsigned cum = excl;
#pragma unroll
                    for (int i = 7; i >= 0; i--) {
                        unsigned cnt = h[i];
                        if (cum + cnt >= (unsigned)kk) {
                            s_pref = pref | ((unsigned)(base + i) << shift);
                            s_kk   = kk - (int)cum;
                            break;
                        }
                        cum += cnt;
                    }
                }
            }
            __syncthreads();
        }
        const unsigned T = s_pref;
        float sum_gt = 0.f;
        for (int p = tid; p < NP; p += THREADS) {
            float v = s_ce[p];
            if (__float_as_uint(v) > T) sum_gt += v;
        }
        sum_gt = warp_sum(sum_gt);
        if (lane == 0) atomicAdd(&s_sumgt, sum_gt);
        __syncthreads();
        if (tid == 0)
            conf_hard = s_sumgt + (float)s_kk * __uint_as_float(T);
    }

    if (tid == 0) {
        g_conf_p[bc] = s_cpsum + conf_hard;
        g_l1_p[bc]   = s_l1sum;
        g_np_p[bc]   = (float)npos;
    }
}

__global__ void mb_finalize_kernel(float* __restrict__ out) {
    __shared__ float s_loss[NC];
    int c = threadIdx.x;
    if (c < NC) {
        float conf = 0.f, l1 = 0.f, np = 0.f;
        for (int n = 0; n < NB; n++) {
            int bc = n * NC + c;
            conf += g_conf_p[bc];
            l1   += g_l1_p[bc];
            np   += g_np_p[bc];
        }
        float v = 0.f;
        if (np > 0.f)
            v = (conf + l1 / fmaxf(np * 4.f, 1.f)) / fmaxf(np, 1.f);
        s_loss[c] = v;
    }
    __syncthreads();
    if (c == 0) {
        float s = 0.f;
        for (int i = 0; i < NC; i++) s += s_loss[i];
        out[0] = s / (float)NC;
    }
}

extern "C" void kernel_launch(void* const* d_in, const int* in_sizes, int n_in,
                              void* d_out, int out_size) {
    const float* ploc   = (const float*)d_in[0];
    const float* pscore = (const float*)d_in[1];
    const float* boxes  = (const float*)d_in[2];
    const int*   labels = (const int*)d_in[3];
    const float* priors = (const float*)d_in[4];
    float* out = (float*)d_out;

    mb_main_kernel<<<NROWS, THREADS>>>(ploc, pscore, boxes, labels, priors);
    mb_finalize_kernel<<<1, 32>>>(out);
}